// round 10
// baseline (speedup 1.0000x reference)
#include <cuda_runtime.h>

// Fixed problem shape
#define BB    256
#define TT    2048
#define HID   20
#define EMB   10
#define VOCAB 128

#define NROW  2              // batch rows per block (f32x2-packed in producer)
#define RING  128            // ring slots per row (power of 2)
#define TILE  32             // timesteps per publish/consume tile
#define NTILES (TT / TILE)   // 64 per row -> 128 consumer tiles per block
#define NCONS 3              // warps 0..2 consume; warp 3 produces

typedef unsigned long long ull;

// ---- packed f32x2 helpers (FFMA2 — only reachable via PTX) --------------
__device__ __forceinline__ ull pk(float lo, float hi) {
    ull r; asm("mov.b64 %0, {%1,%2};" : "=l"(r) : "f"(lo), "f"(hi)); return r;
}
__device__ __forceinline__ void upk(float& lo, float& hi, ull v) {
    asm("mov.b64 {%0,%1}, %2;" : "=f"(lo), "=f"(hi) : "l"(v));
}
__device__ __forceinline__ void dfma(ull& d, ull a, ull b) {
    asm("fma.rn.f32x2 %0, %1, %2, %0;" : "+l"(d) : "l"(a), "l"(b));
}
__device__ __forceinline__ ull dadd(ull a, ull b) {
    ull r; asm("add.rn.f32x2 %0, %1, %2;" : "=l"(r) : "l"(a), "l"(b)); return r;
}

// HW tanh (MUFU.TANH): measured rel err ~4e-6 end-to-end through 2048 steps
__device__ __forceinline__ float tanh_hw(float z) {
    float r; asm("tanh.approx.f32 %0, %1;" : "=f"(r) : "f"(z)); return r;
}

// ---------------------------------------------------------------------------
// One block per TWO batch rows, 128 threads.
// Warp 3 (producer): BOTH recurrences packed as f32x2 (lo=row A, hi=row B);
//   h exchanged through an interleaved pair-ring; scalar per-row rings written
//   for the consumers. Zero per-step address arithmetic (chunk-peeled bases).
// Warps 0-2 (consumers): project finished 32-step tiles (both rows) to vocab.
// ---------------------------------------------------------------------------
__global__ void __launch_bounds__(128, 1) fused_rnn_kernel(
    const int*   __restrict__ inputs,
    const float* __restrict__ emb,
    const float* __restrict__ W_ih,
    const float* __restrict__ W_hh,
    const float* __restrict__ b_ih,
    const float* __restrict__ b_hh,
    const float* __restrict__ W_out,
    const float* __restrict__ b_out,
    float*       __restrict__ out)
{
    __shared__ __align__(16) float s_proj[VOCAB * HID];        // 10 KB
    __shared__ __align__(16) float s_iring[RING * HID * 2];    // 20 KB, (A,B) pairs
    __shared__ __align__(16) float s_ring[NROW][RING * HID];   // 2 x 10 KB scalar
    __shared__ int s_idx[NROW][TILE];
    __shared__ volatile int s_prog;            // steps produced (both rows, lockstep)
    __shared__ volatile int s_next[NCONS];     // next tile index per consumer warp

    const int tid  = threadIdx.x;
    const int lane = tid & 31;
    const int wid  = tid >> 5;
    const int b    = blockIdx.x;               // handles rows 2b, 2b+1

    // proj[v][j] = b_ih[j]+b_hh[j] + sum_e emb[v][e]*W_ih[j][e]
    for (int i = tid; i < VOCAB * HID; i += 128) {
        int v = i / HID, j = i - v * HID;
        float acc = b_ih[j] + b_hh[j];
#pragma unroll
        for (int e = 0; e < EMB; ++e)
            acc = fmaf(emb[v * EMB + e], W_ih[j * EMB + e], acc);
        s_proj[i] = acc;
    }
    if (tid == 0) s_prog = 0;
    if (tid < NCONS) s_next[tid] = tid;
    if (tid < HID) {                                  // h_{-1} = 0 everywhere
        s_ring[0][(RING - 1) * HID + tid] = 0.0f;
        s_ring[1][(RING - 1) * HID + tid] = 0.0f;
        s_iring[(RING - 1) * HID * 2 + 2 * tid + 0] = 0.0f;
        s_iring[(RING - 1) * HID * 2 + 2 * tid + 1] = 0.0f;
    }
    __syncthreads();

    if (wid == NCONS) {
        // ===== PRODUCER (warp 3): rows A,B packed into f32x2 lanes =========
        const int  j   = lane;
        const bool act = (j < HID);
        const int  jx  = act ? j : 0;

        // W_hh row j, each scalar replicated into both f32x2 halves
        ull w2[HID];
        if (act) {
#pragma unroll
            for (int k = 0; k < HID; ++k) {
                float wv = W_hh[j * HID + k];
                w2[k] = pk(wv, wv);
            }
        } else {
#pragma unroll
            for (int k = 0; k < HID; ++k) w2[k] = 0ull;
        }

        const int* inp0 = inputs + (size_t)(2 * b + 0) * TT;
        const int* inp1 = inputs + (size_t)(2 * b + 1) * TT;

        // prologue: stage chunk-0 indices for both rows, prefetch x_0
        s_idx[0][lane] = inp0[lane];
        s_idx[1][lane] = inp1[lane];
        __syncwarp();
        float x0 = s_proj[s_idx[0][0] * HID + jx];
        float x1 = s_proj[s_idx[1][0] * HID + jx];

        for (int tc = 0; tc < TT; tc += TILE) {
            int ni0 = (tc + TILE < TT) ? inp0[tc + TILE + lane] : 0;
            int ni1 = (tc + TILE < TT) ? inp1[tc + TILE + lane] : 0;

            // back-pressure: ring slots [tc, tc+32) must be consumed
            int needSteps = tc + TILE - RING;
            if (needSteps > 0) {
                int needTiles = (needSteps + TILE - 1) >> 5;
                if (lane == 0) {
                    for (;;) {
                        int m = s_next[0];
#pragma unroll
                        for (int k = 1; k < NCONS; ++k) m = min(m, s_next[k]);
                        if ((m >> 1) >= needTiles) break;
                        __nanosleep(128);
                    }
                }
                __syncwarp();
            }

            // per-chunk base pointers; all per-step offsets are immediates.
            // slots tc..tc+31 never wrap (tc mod 128 in {0,32,64,96}); only the
            // tt=0 read of slot (tc-1) can wrap -> peeled pointer.
            const int  cbase = tc & (RING - 1);
            const float* rprev = s_iring + ((tc + RING - 1) & (RING - 1)) * (2 * HID);
            const float* rbase = s_iring + cbase * (2 * HID);
            float*       wbase = s_iring + cbase * (2 * HID) + 2 * j;
            float*       wsA   = s_ring[0] + cbase * HID + j;
            float*       wsB   = s_ring[1] + cbase * HID + j;

#pragma unroll
            for (int tt = 0; tt < TILE; ++tt) {
                // h pairs for step t-1: 10 x LDS.128, immediate offsets
                const ulonglong2* hp = (const ulonglong2*)
                    ((tt == 0) ? rprev : (rbase + (tt - 1) * (2 * HID)));
                ulonglong2 q0 = hp[0], q1 = hp[1], q2 = hp[2], q3 = hp[3], q4 = hp[4];
                ulonglong2 q5 = hp[5], q6 = hp[6], q7 = hp[7], q8 = hp[8], q9 = hp[9];

                // prefetch next step's x for both rows (off the chain)
                float nx0 = x0, nx1 = x1;
                if (tt < TILE - 1) {
                    nx0 = s_proj[s_idx[0][tt + 1] * HID + jx];
                    nx1 = s_proj[s_idx[1][tt + 1] * HID + jx];
                }

                // z = (x^A, x^B) + sum_k (w_jk, w_jk) * (h^A_k, h^B_k)
                ull c0 = pk(x0, x1);
                ull c1 = pk(0.f, 0.f), c2 = pk(0.f, 0.f), c3 = pk(0.f, 0.f);
                dfma(c0, w2[0],  q0.x); dfma(c1, w2[1],  q0.y);
                dfma(c2, w2[2],  q1.x); dfma(c3, w2[3],  q1.y);
                dfma(c0, w2[4],  q2.x); dfma(c1, w2[5],  q2.y);
                dfma(c2, w2[6],  q3.x); dfma(c3, w2[7],  q3.y);
                dfma(c0, w2[8],  q4.x); dfma(c1, w2[9],  q4.y);
                dfma(c2, w2[10], q5.x); dfma(c3, w2[11], q5.y);
                dfma(c0, w2[12], q6.x); dfma(c1, w2[13], q6.y);
                dfma(c2, w2[14], q7.x); dfma(c3, w2[15], q7.y);
                dfma(c0, w2[16], q8.x); dfma(c1, w2[17], q8.y);
                dfma(c2, w2[18], q9.x); dfma(c3, w2[19], q9.y);
                ull d = dadd(dadd(c0, c1), dadd(c2, c3));
                float zA, zB; upk(zA, zB, d);        // register aliasing

                float hA = tanh_hw(zA);
                float hB = tanh_hw(zB);
                if (act) {
                    // interleaved pair for the producer's own next-step read
                    *(float2*)(wbase + tt * (2 * HID)) = make_float2(hA, hB);
                    // scalar copies for the consumers
                    wsA[tt * HID] = hA;
                    wsB[tt * HID] = hB;
                }
                x0 = nx0; x1 = nx1;
                // no per-step __syncwarp: same-warp STS->LDS is LSU-ordered
            }

            // publish superstep; stage next chunks' indices
            __syncwarp();
            __threadfence_block();
            if (lane == 0) s_prog = tc + TILE;
            s_idx[0][lane] = ni0;
            s_idx[1][lane] = ni1;
            __syncwarp();
            x0 = s_proj[s_idx[0][0] * HID + jx];
            x1 = s_proj[s_idx[1][0] * HID + jx];
        }
    } else {
        // ============ CONSUMERS (warps 0-2): tiles over {row} x {t-chunk}
        const int v0 = lane * 4;          // 32 lanes x 4 vocab = 128
        ull wo[4][10];
        ull bo[4];
#pragma unroll
        for (int r = 0; r < 4; ++r) {
            const float4* wr = (const float4*)(W_out + (v0 + r) * HID);
#pragma unroll
            for (int q = 0; q < 5; ++q) {
                float4 f = wr[q];
                wo[r][2*q]   = pk(f.x, f.y);
                wo[r][2*q+1] = pk(f.z, f.w);
            }
            bo[r] = pk(b_out[v0 + r], 0.0f);
        }

        for (int tl = wid; tl < NROW * NTILES; tl += NCONS) {
            const int row  = tl & 1;
            const int t0   = (tl >> 1) * TILE;
            const int tend = t0 + TILE;
            if (lane == 0) {
                while (s_prog < tend) __nanosleep(128);
            }
            __syncwarp();
            __threadfence_block();

            const float* ring = s_ring[row];
            float* outp = out + ((size_t)(2 * b + row) * TT + t0) * VOCAB + v0;
#pragma unroll 4
            for (int tt = 0; tt < TILE; ++tt) {
                const ulonglong2* hp = (const ulonglong2*)
                    (ring + ((t0 + tt) & (RING - 1)) * HID);
                ulonglong2 p0 = hp[0], p1 = hp[1], p2 = hp[2], p3 = hp[3], p4 = hp[4];

                float4 res;
#pragma unroll
                for (int r = 0; r < 4; ++r) {
                    ull acc = bo[r];
                    dfma(acc, wo[r][0], p0.x); dfma(acc, wo[r][1], p0.y);
                    dfma(acc, wo[r][2], p1.x); dfma(acc, wo[r][3], p1.y);
                    dfma(acc, wo[r][4], p2.x); dfma(acc, wo[r][5], p2.y);
                    dfma(acc, wo[r][6], p3.x); dfma(acc, wo[r][7], p3.y);
                    dfma(acc, wo[r][8], p4.x); dfma(acc, wo[r][9], p4.y);
                    float lo, hi; upk(lo, hi, acc);
                    (&res.x)[r] = lo + hi;
                }
                *(float4*)(outp + (size_t)tt * VOCAB) = res;   // 512B coalesced
            }
            __syncwarp();
            if (lane == 0) s_next[wid] = tl + NCONS;
        }
    }
}

// ---------------------------------------------------------------------------
// Inputs (metadata order):
// 0: inputs int32 [256,2048]  1: emb [128,10]  2: W_ih [20,10]  3: W_hh [20,20]
// 4: b_ih [20]  5: b_hh [20]  6: W_out [128,20]  7: b_out [128]
// Output: float32 [256,2048,128]
// ---------------------------------------------------------------------------
extern "C" void kernel_launch(void* const* d_in, const int* in_sizes, int n_in,
                              void* d_out, int out_size) {
    const int*   inputs = (const int*)d_in[0];
    const float* emb    = (const float*)d_in[1];
    const float* W_ih   = (const float*)d_in[2];
    const float* W_hh   = (const float*)d_in[3];
    const float* b_ih   = (const float*)d_in[4];
    const float* b_hh   = (const float*)d_in[5];
    const float* W_out  = (const float*)d_in[6];
    const float* b_out  = (const float*)d_in[7];
    float*       out    = (float*)d_out;

    fused_rnn_kernel<<<BB / NROW, 128>>>(inputs, emb, W_ih, W_hh, b_ih, b_hh,
                                         W_out, b_out, out);
}